// round 2
// baseline (speedup 1.0000x reference)
#include <cuda_runtime.h>
#include <math.h>

// Problem constants
#define B_   256
#define R_   2048
#define M_   65536
#define L_   64
#define H_   4
#define BH_  1024

typedef unsigned long long ull;

// ---------------- device scratch (no allocs allowed) ----------------
__device__ float g_memT[64 * 65536];      // memory transposed [l][m], 16 MB
__device__ float g_rsT[2048 * 256];       // reservoir transposed [k][b], 2 MB
__device__ float g_WkT[2048 * 256];       // Wk transposed [k][n], 2 MB
__device__ float g_pk[16 * 256 * 256];    // split-K partials for keys, 4 MB
__device__ float g_skeysT[64 * 1024];     // scaled keys transposed [l][bh], 256 KB
__device__ float g_sumsP[1024 * 512];     // per (row, m-tile) partial expsums, 2 MB
__device__ float g_invsum[1024];          // 1/rowsum

// ---------------- packed fp32 helpers (fma.rn.f32x2) ----------------
__device__ __forceinline__ ull packdup(float x) {
    ull r; asm("mov.b64 %0, {%1, %1};" : "=l"(r) : "f"(x)); return r;
}
__device__ __forceinline__ ull pack2(float x, float y) {
    ull r; asm("mov.b64 %0, {%1, %2};" : "=l"(r) : "f"(x), "f"(y)); return r;
}
__device__ __forceinline__ void fma2(ull &d, ull a, ull b) {
    asm("fma.rn.f32x2 %0, %1, %2, %0;" : "+l"(d) : "l"(a), "l"(b));
}
__device__ __forceinline__ float2 unpack2(ull v) {
    float2 f; asm("mov.b64 {%0, %1}, %2;" : "=f"(f.x), "=f"(f.y) : "l"(v)); return f;
}

// ---------------- generic 32x32 transpose ----------------
__device__ __forceinline__ void transpose_body(const float* __restrict__ in,
                                               float* __restrict__ out,
                                               int rows, int cols) {
    __shared__ float t[32][33];
    int c0 = blockIdx.x * 32, r0 = blockIdx.y * 32;
#pragma unroll
    for (int j = 0; j < 4; j++)
        t[threadIdx.y + 8 * j][threadIdx.x] =
            in[(size_t)(r0 + threadIdx.y + 8 * j) * cols + c0 + threadIdx.x];
    __syncthreads();
#pragma unroll
    for (int j = 0; j < 4; j++)
        out[(size_t)(c0 + threadIdx.y + 8 * j) * rows + r0 + threadIdx.x] =
            t[threadIdx.x][threadIdx.y + 8 * j];
}

__global__ void t_mem(const float* __restrict__ in) { transpose_body(in, g_memT, 65536, 64); }
__global__ void t_rs (const float* __restrict__ in) { transpose_body(in, g_rsT,  256, 2048); }
__global__ void t_wk (const float* __restrict__ in) { transpose_body(in, g_WkT,  256, 2048); }

// ---------------- kernel 1a: split-K GEMM for key projection ----------------
// partial[z][b][n] = sum_{k in chunk z} rs[b][k] * Wk[n][k]
// grid (2 n-tiles, 2 b-tiles, 16 k-splits), 256 threads, 128x128 tile, 8x8/thread
__global__ __launch_bounds__(256, 2) void k1a_keys_gemm() {
    int n0 = blockIdx.x * 128, b0 = blockIdx.y * 128, kb = blockIdx.z * 128;
    int tid = threadIdx.x, tx = tid & 15, ty = tid >> 4;
    __shared__ float At[32][128];
    __shared__ float Bt[32][128];
    ull acc[8][4];
#pragma unroll
    for (int i = 0; i < 8; i++)
#pragma unroll
        for (int j = 0; j < 4; j++) acc[i][j] = 0ull;

    for (int kc = 0; kc < 128; kc += 32) {
#pragma unroll
        for (int it = 0; it < 4; it++) {
            int idx = tid + it * 256;
            int r = idx >> 5, c = (idx & 31) * 4;
            *(float4*)&At[r][c] = *(const float4*)&g_rsT[(size_t)(kb + kc + r) * 256 + b0 + c];
            *(float4*)&Bt[r][c] = *(const float4*)&g_WkT[(size_t)(kb + kc + r) * 256 + n0 + c];
        }
        __syncthreads();
#pragma unroll 8
        for (int k = 0; k < 32; k++) {
            float4 a0 = *(float4*)&At[k][ty * 4];
            float4 a1 = *(float4*)&At[k][64 + ty * 4];
            float4 b0v = *(float4*)&Bt[k][tx * 4];
            float4 b1v = *(float4*)&Bt[k][64 + tx * 4];
            ull bp0 = pack2(b0v.x, b0v.y), bp1 = pack2(b0v.z, b0v.w);
            ull bp2 = pack2(b1v.x, b1v.y), bp3 = pack2(b1v.z, b1v.w);
            float av[8] = {a0.x, a0.y, a0.z, a0.w, a1.x, a1.y, a1.z, a1.w};
#pragma unroll
            for (int i = 0; i < 8; i++) {
                ull ad = packdup(av[i]);
                fma2(acc[i][0], ad, bp0); fma2(acc[i][1], ad, bp1);
                fma2(acc[i][2], ad, bp2); fma2(acc[i][3], ad, bp3);
            }
        }
        __syncthreads();
    }
    int z = blockIdx.z;
#pragma unroll
    for (int i = 0; i < 8; i++) {
        int rl = (i < 4) ? (ty * 4 + i) : (64 + ty * 4 + (i - 4));
        float2 v0 = unpack2(acc[i][0]), v1 = unpack2(acc[i][1]);
        float2 v2 = unpack2(acc[i][2]), v3 = unpack2(acc[i][3]);
        size_t base = (size_t)z * 65536 + (size_t)(b0 + rl) * 256 + n0;
        float4 o0 = make_float4(v0.x, v0.y, v1.x, v1.y);
        float4 o1 = make_float4(v2.x, v2.y, v3.x, v3.y);
        *(float4*)&g_pk[base + tx * 4] = o0;
        *(float4*)&g_pk[base + 64 + tx * 4] = o1;
    }
}

// ---------------- kernel 1b: finalize keys -> scaled transposed keys ----------------
// scale = relu(rs[b].Wb[h] + bb[h]) / ||key||;  g_skeysT[l][bh] = key[l]*scale
__global__ void k1b_finalize(const float* __restrict__ rs, const float* __restrict__ Wb,
                             const float* __restrict__ bk, const float* __restrict__ bb) {
    int bh = blockIdx.x;
    int b = bh >> 2, h = bh & 3;
    int l = threadIdx.x;              // 64 threads
    int n = h * 64 + l;

    float key = bk[n];
#pragma unroll
    for (int s = 0; s < 16; s++) key += g_pk[(size_t)s * 65536 + b * 256 + n];

    float bp = 0.f;
#pragma unroll 8
    for (int i = 0; i < 32; i++)
        bp += rs[b * 2048 + l + 64 * i] * Wb[h * 2048 + l + 64 * i];

    __shared__ float s1[64], s2[64];
    s1[l] = key * key; s2[l] = bp;
    __syncthreads();
    for (int o = 32; o > 0; o >>= 1) {
        if (l < o) { s1[l] += s1[l + o]; s2[l] += s2[l + o]; }
        __syncthreads();
    }
    float beta = s2[0] + bb[h];
    beta = beta > 0.f ? beta : 0.f;
    float scale = beta * rsqrtf(s1[0]);
    g_skeysT[l * 1024 + bh] = key * scale;
}

// ---------------- kernel 2: main GEMM + exp + partial row sums ----------------
// out[bh][m] = exp( dot(skeys[bh], mem[m]) )  ; deterministic per-(row, m-tile) partials
// grid (512 m-tiles, 8 bh-tiles), 256 threads, 128x128 tile, 8x8/thread, K=64
__global__ __launch_bounds__(256, 2) void k2_main(float* __restrict__ out) {
    int mt = blockIdx.x, bt = blockIdx.y;
    int m0 = mt * 128, bh0 = bt * 128;
    int tid = threadIdx.x, tx = tid & 15, ty = tid >> 4;
    __shared__ float skT[32][128];   // [k][bh]
    __shared__ float mT[32][128];    // [k][m]
    ull acc[8][4];
#pragma unroll
    for (int i = 0; i < 8; i++)
#pragma unroll
        for (int j = 0; j < 4; j++) acc[i][j] = 0ull;

    for (int kc = 0; kc < 64; kc += 32) {
#pragma unroll
        for (int it = 0; it < 4; it++) {
            int idx = tid + it * 256;
            int r = idx >> 5, c = (idx & 31) * 4;
            *(float4*)&skT[r][c] = *(const float4*)&g_skeysT[(size_t)(kc + r) * 1024 + bh0 + c];
            *(float4*)&mT[r][c]  = *(const float4*)&g_memT[(size_t)(kc + r) * 65536 + m0 + c];
        }
        __syncthreads();
#pragma unroll 8
        for (int k = 0; k < 32; k++) {
            float4 a0 = *(float4*)&skT[k][ty * 4];
            float4 a1 = *(float4*)&skT[k][64 + ty * 4];
            float4 b0v = *(float4*)&mT[k][tx * 4];
            float4 b1v = *(float4*)&mT[k][64 + tx * 4];
            ull bp0 = pack2(b0v.x, b0v.y), bp1 = pack2(b0v.z, b0v.w);
            ull bp2 = pack2(b1v.x, b1v.y), bp3 = pack2(b1v.z, b1v.w);
            float av[8] = {a0.x, a0.y, a0.z, a0.w, a1.x, a1.y, a1.z, a1.w};
#pragma unroll
            for (int i = 0; i < 8; i++) {
                ull ad = packdup(av[i]);
                fma2(acc[i][0], ad, bp0); fma2(acc[i][1], ad, bp1);
                fma2(acc[i][2], ad, bp2); fma2(acc[i][3], ad, bp3);
            }
        }
        __syncthreads();
    }

    // epilogue: exp + store + per-thread row sums (no max needed: logits bounded)
    float rsum[8];
#pragma unroll
    for (int i = 0; i < 8; i++) {
        int rl = (i < 4) ? (ty * 4 + i) : (64 + ty * 4 + (i - 4));
        float2 v0 = unpack2(acc[i][0]), v1 = unpack2(acc[i][1]);
        float2 v2 = unpack2(acc[i][2]), v3 = unpack2(acc[i][3]);
        float e0 = __expf(v0.x), e1 = __expf(v0.y), e2 = __expf(v1.x), e3 = __expf(v1.y);
        float e4 = __expf(v2.x), e5 = __expf(v2.y), e6 = __expf(v3.x), e7 = __expf(v3.y);
        size_t base = (size_t)(bh0 + rl) * 65536 + m0;
        *(float4*)&out[base + tx * 4]      = make_float4(e0, e1, e2, e3);
        *(float4*)&out[base + 64 + tx * 4] = make_float4(e4, e5, e6, e7);
        rsum[i] = ((e0 + e1) + (e2 + e3)) + ((e4 + e5) + (e6 + e7));
    }

    // deterministic cross-thread reduction for the 128 rows of this block
    __syncthreads();
    float* ps = &skT[0][0];   // reuse 16 KB smem as ps[16][128]
#pragma unroll
    for (int i = 0; i < 8; i++) {
        int rl = (i < 4) ? (ty * 4 + i) : (64 + ty * 4 + (i - 4));
        ps[tx * 128 + rl] = rsum[i];
    }
    __syncthreads();
    if (tid < 128) {
        float s = 0.f;
#pragma unroll
        for (int t = 0; t < 16; t++) s += ps[t * 128 + tid];
        g_sumsP[(size_t)(bh0 + tid) * 512 + mt] = s;
    }
}

// ---------------- kernel 3: reduce partial sums -> 1/rowsum ----------------
__global__ void k3_reduce() {
    int bh = blockIdx.x, t = threadIdx.x;   // 128 threads
    float s = 0.f;
#pragma unroll
    for (int j = 0; j < 4; j++) s += g_sumsP[(size_t)bh * 512 + t + 128 * j];
    __shared__ float red[128];
    red[t] = s;
    __syncthreads();
    for (int o = 64; o > 0; o >>= 1) {
        if (t < o) red[t] += red[t + o];
        __syncthreads();
    }
    if (t == 0) g_invsum[bh] = 1.0f / red[0];
}

// ---------------- kernel 4: normalize ----------------
__global__ void k4_normalize(float* __restrict__ out) {
    size_t i4 = (size_t)blockIdx.x * 256 + threadIdx.x;   // float4 index
    int row = (int)(i4 >> 14);                            // 16384 float4 per row
    float s = g_invsum[row];
    float4 v = ((float4*)out)[i4];
    v.x *= s; v.y *= s; v.z *= s; v.w *= s;
    ((float4*)out)[i4] = v;
}

// ---------------- launch ----------------
extern "C" void kernel_launch(void* const* d_in, const int* in_sizes, int n_in,
                              void* d_out, int out_size) {
    const float* rs  = (const float*)d_in[0];   // [256, 2048]
    const float* mem = (const float*)d_in[1];   // [1, 65536, 64]
    const float* Wk  = (const float*)d_in[2];   // [256, 2048]
    const float* bk  = (const float*)d_in[3];   // [256]
    const float* Wb  = (const float*)d_in[4];   // [4, 2048]
    const float* bb  = (const float*)d_in[5];   // [4]
    float* out = (float*)d_out;                 // [256, 4, 65536]

    (void)in_sizes; (void)n_in; (void)out_size;

    dim3 tb(32, 8);
    t_mem<<<dim3(2, 2048), tb>>>(mem);
    t_rs <<<dim3(64, 8),   tb>>>(rs);
    t_wk <<<dim3(64, 8),   tb>>>(Wk);

    k1a_keys_gemm<<<dim3(2, 2, 16), 256>>>();
    k1b_finalize<<<1024, 64>>>(rs, Wb, bk, bb);

    k2_main<<<dim3(512, 8), 256>>>(out);
    k3_reduce<<<1024, 128>>>();
    k4_normalize<<<65536, 256>>>(out);
}

// round 4
// speedup vs baseline: 1.3178x; 1.3178x over previous
#include <cuda_runtime.h>
#include <cuda_bf16.h>
#include <math.h>
#include <cstdint>

// Shapes: B=256, R=2048, M=65536, L=64, H=4, BH=1024
typedef unsigned long long ull;

// ---------------- device scratch ----------------
__device__ float g_rsT[2048 * 256];                 // reservoir transposed [k][b]
__device__ float g_WkT[2048 * 256];                 // Wk transposed [k][n]
__device__ float g_pk[32 * 256 * 256];              // split-K partials for keys
__device__ __nv_bfloat16 g_key_hi[1024 * 64];       // scaled keys, bf16 hi  [bh][l]
__device__ __nv_bfloat16 g_key_lo[1024 * 64];       // scaled keys, bf16 lo
__device__ __nv_bfloat16 g_mem_hi[65536 * 64];      // memory, bf16 hi [m][l]
__device__ __nv_bfloat16 g_mem_lo[65536 * 64];      // memory, bf16 lo
__device__ float g_sumsP[1024 * 512];               // per (row, m-tile) partial expsums
__device__ float g_invsum[1024];

// ---------------- packed fp32 helpers (k1a) ----------------
__device__ __forceinline__ ull packdup(float x) {
    ull r; asm("mov.b64 %0, {%1, %1};" : "=l"(r) : "f"(x)); return r;
}
__device__ __forceinline__ ull pack2(float x, float y) {
    ull r; asm("mov.b64 %0, {%1, %2};" : "=l"(r) : "f"(x), "f"(y)); return r;
}
__device__ __forceinline__ void fma2(ull &d, ull a, ull b) {
    asm("fma.rn.f32x2 %0, %1, %2, %0;" : "+l"(d) : "l"(a), "l"(b));
}
__device__ __forceinline__ float2 unpack2(ull v) {
    float2 f; asm("mov.b64 {%0, %1}, %2;" : "=f"(f.x), "=f"(f.y) : "l"(v)); return f;
}

// ---------------- HMMA helper ----------------
__device__ __forceinline__ void mma_bf16(float* d, uint32_t a0, uint32_t a1,
                                         uint32_t a2, uint32_t a3,
                                         uint32_t b0, uint32_t b1) {
    asm volatile(
        "mma.sync.aligned.m16n8k16.row.col.f32.bf16.bf16.f32 "
        "{%0,%1,%2,%3}, {%4,%5,%6,%7}, {%8,%9}, {%0,%1,%2,%3};"
        : "+f"(d[0]), "+f"(d[1]), "+f"(d[2]), "+f"(d[3])
        : "r"(a0), "r"(a1), "r"(a2), "r"(a3), "r"(b0), "r"(b1));
}

// ---------------- transposes for k1 ----------------
__device__ __forceinline__ void transpose_body(const float* __restrict__ in,
                                               float* __restrict__ out, int rows, int cols) {
    __shared__ float t[32][33];
    int c0 = blockIdx.x * 32, r0 = blockIdx.y * 32;
#pragma unroll
    for (int j = 0; j < 4; j++)
        t[threadIdx.y + 8 * j][threadIdx.x] =
            in[(size_t)(r0 + threadIdx.y + 8 * j) * cols + c0 + threadIdx.x];
    __syncthreads();
#pragma unroll
    for (int j = 0; j < 4; j++)
        out[(size_t)(c0 + threadIdx.y + 8 * j) * rows + r0 + threadIdx.x] =
            t[threadIdx.x][threadIdx.y + 8 * j];
}
__global__ void t_rs(const float* __restrict__ in) { transpose_body(in, g_rsT, 256, 2048); }
__global__ void t_wk(const float* __restrict__ in) { transpose_body(in, g_WkT, 256, 2048); }

// ---------------- memory -> bf16 hi/lo ----------------
__global__ void conv_mem(const float* __restrict__ in) {
    size_t i = (size_t)blockIdx.x * 256 + threadIdx.x;     // group of 8 floats
    const float4* p = (const float4*)in + i * 2;
    float4 a = p[0], b = p[1];
    float v[8] = {a.x, a.y, a.z, a.w, b.x, b.y, b.z, b.w};
    __align__(16) __nv_bfloat16 hh[8], ll[8];
#pragma unroll
    for (int j = 0; j < 8; j++) {
        hh[j] = __float2bfloat16_rn(v[j]);
        ll[j] = __float2bfloat16_rn(v[j] - __bfloat162float(hh[j]));
    }
    *(uint4*)&g_mem_hi[i * 8] = *(uint4*)hh;
    *(uint4*)&g_mem_lo[i * 8] = *(uint4*)ll;
}

// ---------------- k1a: split-K GEMM for key projection ----------------
// grid (2 n-tiles, 2 b-tiles, 32 k-splits of 64), 256 threads, 128x128 tile
__global__ __launch_bounds__(256, 2) void k1a_keys_gemm() {
    int n0 = blockIdx.x * 128, b0 = blockIdx.y * 128, kb = blockIdx.z * 64;
    int tid = threadIdx.x, tx = tid & 15, ty = tid >> 4;
    __shared__ float At[32][128];
    __shared__ float Bt[32][128];
    ull acc[8][4];
#pragma unroll
    for (int i = 0; i < 8; i++)
#pragma unroll
        for (int j = 0; j < 4; j++) acc[i][j] = 0ull;

    for (int kc = 0; kc < 64; kc += 32) {
#pragma unroll
        for (int it = 0; it < 4; it++) {
            int idx = tid + it * 256;
            int r = idx >> 5, c = (idx & 31) * 4;
            *(float4*)&At[r][c] = *(const float4*)&g_rsT[(size_t)(kb + kc + r) * 256 + b0 + c];
            *(float4*)&Bt[r][c] = *(const float4*)&g_WkT[(size_t)(kb + kc + r) * 256 + n0 + c];
        }
        __syncthreads();
#pragma unroll 8
        for (int k = 0; k < 32; k++) {
            float4 a0 = *(float4*)&At[k][ty * 4];
            float4 a1 = *(float4*)&At[k][64 + ty * 4];
            float4 b0v = *(float4*)&Bt[k][tx * 4];
            float4 b1v = *(float4*)&Bt[k][64 + tx * 4];
            ull bp0 = pack2(b0v.x, b0v.y), bp1 = pack2(b0v.z, b0v.w);
            ull bp2 = pack2(b1v.x, b1v.y), bp3 = pack2(b1v.z, b1v.w);
            float av[8] = {a0.x, a0.y, a0.z, a0.w, a1.x, a1.y, a1.z, a1.w};
#pragma unroll
            for (int i = 0; i < 8; i++) {
                ull ad = packdup(av[i]);
                fma2(acc[i][0], ad, bp0); fma2(acc[i][1], ad, bp1);
                fma2(acc[i][2], ad, bp2); fma2(acc[i][3], ad, bp3);
            }
        }
        __syncthreads();
    }
    int z = blockIdx.z;
#pragma unroll
    for (int i = 0; i < 8; i++) {
        int rl = (i < 4) ? (ty * 4 + i) : (64 + ty * 4 + (i - 4));
        float2 v0 = unpack2(acc[i][0]), v1 = unpack2(acc[i][1]);
        float2 v2 = unpack2(acc[i][2]), v3 = unpack2(acc[i][3]);
        size_t base = (size_t)z * 65536 + (size_t)(b0 + rl) * 256 + n0;
        *(float4*)&g_pk[base + tx * 4]      = make_float4(v0.x, v0.y, v1.x, v1.y);
        *(float4*)&g_pk[base + 64 + tx * 4] = make_float4(v2.x, v2.y, v3.x, v3.y);
    }
}

// ---------------- k1b: finalize -> scaled bf16 hi/lo keys [bh][64] ----------------
__global__ void k1b_finalize(const float* __restrict__ rs, const float* __restrict__ Wb,
                             const float* __restrict__ bk, const float* __restrict__ bb) {
    int bh = blockIdx.x;
    int b = bh >> 2, h = bh & 3;
    int l = threadIdx.x;              // 64 threads
    int n = h * 64 + l;

    float key = bk[n];
#pragma unroll
    for (int s = 0; s < 32; s++) key += g_pk[(size_t)s * 65536 + b * 256 + n];

    float bp = 0.f;
#pragma unroll 8
    for (int i = 0; i < 32; i++)
        bp += rs[b * 2048 + l + 64 * i] * Wb[h * 2048 + l + 64 * i];

    __shared__ float s1[64], s2[64];
    s1[l] = key * key; s2[l] = bp;
    __syncthreads();
    for (int o = 32; o > 0; o >>= 1) {
        if (l < o) { s1[l] += s1[l + o]; s2[l] += s2[l + o]; }
        __syncthreads();
    }
    float beta = s2[0] + bb[h];
    beta = beta > 0.f ? beta : 0.f;
    float sk = key * (beta * rsqrtf(s1[0]));
    __nv_bfloat16 hi = __float2bfloat16_rn(sk);
    __nv_bfloat16 lo = __float2bfloat16_rn(sk - __bfloat162float(hi));
    g_key_hi[bh * 64 + l] = hi;
    g_key_lo[bh * 64 + l] = lo;
}

// ---------------- k2: HMMA GEMM (128bh x 128m x K64, 3-term bf16 split) ----------------
// PASS 0: exp row-sum partials only.  PASS 1: write exp(d) * invsum to out.
// 8 warps in 2x4 grid, warp tile 64x32, mma.m16n8k16, fragments via direct LDS.
static constexpr int ROW_B = 144;                    // smem row stride in bytes (72 bf16)
static constexpr int SM_A_HI = 0;
static constexpr int SM_A_LO = SM_A_HI + 128 * ROW_B;   // 18432
static constexpr int SM_B_HI = SM_A_LO + 128 * ROW_B;   // 36864
static constexpr int SM_B_LO = SM_B_HI + 128 * ROW_B;   // 55296
static constexpr int SMEM_K2 = SM_B_LO + 128 * ROW_B;   // 73728

template <int PASS>
__global__ __launch_bounds__(256, 2) void k2_mma(float* __restrict__ out) {
    extern __shared__ char smem[];
    int tid = threadIdx.x, wid = tid >> 5, lid = tid & 31;
    int wr = wid >> 2, wc = wid & 3;          // warp grid 2x4
    int g = lid >> 2, c = lid & 3;            // groupID / threadID-in-group
    int mt = blockIdx.x, bt = blockIdx.y;
    int m0 = mt * 128, bh0 = bt * 128;

    // ---- fill smem: A = keys (128 rows), B = mem (128 rows); 64 bf16/row -> 8x16B
#pragma unroll
    for (int i = 0; i < 4; i++) {
        int it = tid + i * 256;               // 1024 chunks of 16B
        int r = it >> 3, c16 = it & 7;
        int dof = r * ROW_B + c16 * 16;
        *(uint4*)(smem + SM_A_HI + dof) = ((const uint4*)(g_key_hi + (size_t)(bh0 + r) * 64))[c16];
        *(uint4*)(smem + SM_A_LO + dof) = ((const uint4*)(g_key_lo + (size_t)(bh0 + r) * 64))[c16];
        *(uint4*)(smem + SM_B_HI + dof) = ((const uint4*)(g_mem_hi + (size_t)(m0 + r) * 64))[c16];
        *(uint4*)(smem + SM_B_LO + dof) = ((const uint4*)(g_mem_lo + (size_t)(m0 + r) * 64))[c16];
    }
    __syncthreads();

    float acc[4][4][4];
#pragma unroll
    for (int mi = 0; mi < 4; mi++)
#pragma unroll
        for (int ni = 0; ni < 4; ni++)
#pragma unroll
            for (int q = 0; q < 4; q++) acc[mi][ni][q] = 0.f;

    // 3 product terms: (Ahi,Bhi), (Ahi,Blo), (Alo,Bhi)
#pragma unroll
    for (int t = 0; t < 3; t++) {
        const char* Ab = smem + (t == 2 ? SM_A_LO : SM_A_HI);
        const char* Bb = smem + (t == 1 ? SM_B_LO : SM_B_HI);
#pragma unroll
        for (int kk = 0; kk < 4; kk++) {
            uint32_t af[4][4];
#pragma unroll
            for (int mi = 0; mi < 4; mi++) {
                int r0 = (wr * 64 + mi * 16 + g) * ROW_B + kk * 32 + c * 4;
                af[mi][0] = *(const uint32_t*)(Ab + r0);
                af[mi][1] = *(const uint32_t*)(Ab + r0 + 8 * ROW_B);
                af[mi][2] = *(const uint32_t*)(Ab + r0 + 16);
                af[mi][3] = *(const uint32_t*)(Ab + r0 + 8 * ROW_B + 16);
            }
            uint32_t bfr[4][2];
#pragma unroll
            for (int ni = 0; ni < 4; ni++) {
                int rb = (wc * 32 + ni * 8 + g) * ROW_B + kk * 32 + c * 4;
                bfr[ni][0] = *(const uint32_t*)(Bb + rb);
                bfr[ni][1] = *(const uint32_t*)(Bb + rb + 16);
            }
#pragma unroll
            for (int mi = 0; mi < 4; mi++)
#pragma unroll
                for (int ni = 0; ni < 4; ni++)
                    mma_bf16(acc[mi][ni], af[mi][0], af[mi][1], af[mi][2], af[mi][3],
                             bfr[ni][0], bfr[ni][1]);
        }
    }

    if (PASS == 0) {
        // exp row-sum partials; acc regs: d0 (g,2c), d1 (g,2c+1), d2 (g+8,2c), d3 (g+8,2c+1)
        __syncthreads();
        float* ps = (float*)smem;             // ps[row 128][wc 4]
#pragma unroll
        for (int mi = 0; mi < 4; mi++) {
            float s0 = 0.f, s1 = 0.f;
#pragma unroll
            for (int ni = 0; ni < 4; ni++) {
                s0 += __expf(acc[mi][ni][0]) + __expf(acc[mi][ni][1]);
                s1 += __expf(acc[mi][ni][2]) + __expf(acc[mi][ni][3]);
            }
            s0 += __shfl_xor_sync(0xffffffffu, s0, 1);
            s0 += __shfl_xor_sync(0xffffffffu, s0, 2);
            s1 += __shfl_xor_sync(0xffffffffu, s1, 1);
            s1 += __shfl_xor_sync(0xffffffffu, s1, 2);
            if (c == 0) {
                int r0 = wr * 64 + mi * 16 + g;
                ps[r0 * 4 + wc] = s0;
                ps[(r0 + 8) * 4 + wc] = s1;
            }
        }
        __syncthreads();
        if (tid < 128) {
            float s = (ps[tid * 4 + 0] + ps[tid * 4 + 1]) + (ps[tid * 4 + 2] + ps[tid * 4 + 3]);
            g_sumsP[(size_t)(bh0 + tid) * 512 + mt] = s;
        }
    } else {
#pragma unroll
        for (int mi = 0; mi < 4; mi++) {
            int r0 = bh0 + wr * 64 + mi * 16 + g;
            float i0 = g_invsum[r0], i1 = g_invsum[r0 + 8];
            size_t ob0 = (size_t)r0 * 65536 + m0 + wc * 32;
            size_t ob1 = (size_t)(r0 + 8) * 65536 + m0 + wc * 32;
#pragma unroll
            for (int ni = 0; ni < 4; ni++) {
                int col = ni * 8 + 2 * c;
                float2 v0 = make_float2(__expf(acc[mi][ni][0]) * i0, __expf(acc[mi][ni][1]) * i0);
                float2 v1 = make_float2(__expf(acc[mi][ni][2]) * i1, __expf(acc[mi][ni][3]) * i1);
                *(float2*)&out[ob0 + col] = v0;
                *(float2*)&out[ob1 + col] = v1;
            }
        }
    }
}

// ---------------- k3: reduce partial sums -> 1/rowsum ----------------
__global__ void k3_reduce() {
    int bh = blockIdx.x, t = threadIdx.x;   // 128 threads
    float s = 0.f;
#pragma unroll
    for (int j = 0; j < 4; j++) s += g_sumsP[(size_t)bh * 512 + t + 128 * j];
    __shared__ float red[128];
    red[t] = s;
    __syncthreads();
    for (int o = 64; o > 0; o >>= 1) {
        if (t < o) red[t] += red[t + o];
        __syncthreads();
    }
    if (t == 0) g_invsum[bh] = 1.0f / red[0];
}

// ---------------- launch ----------------
extern "C" void kernel_launch(void* const* d_in, const int* in_sizes, int n_in,
                              void* d_out, int out_size) {
    const float* rs  = (const float*)d_in[0];   // [256, 2048]
    const float* mem = (const float*)d_in[1];   // [1, 65536, 64]
    const float* Wk  = (const float*)d_in[2];   // [256, 2048]
    const float* bk  = (const float*)d_in[3];   // [256]
    const float* Wb  = (const float*)d_in[4];   // [4, 2048]
    const float* bb  = (const float*)d_in[5];   // [4]
    float* out = (float*)d_out;                 // [256, 4, 65536]
    (void)in_sizes; (void)n_in; (void)out_size;

    cudaFuncSetAttribute(k2_mma<0>, cudaFuncAttributeMaxDynamicSharedMemorySize, SMEM_K2);
    cudaFuncSetAttribute(k2_mma<1>, cudaFuncAttributeMaxDynamicSharedMemorySize, SMEM_K2);

    dim3 tb(32, 8);
    conv_mem<<<2048, 256>>>(mem);
    t_rs<<<dim3(64, 8), tb>>>(rs);
    t_wk<<<dim3(64, 8), tb>>>(Wk);

    k1a_keys_gemm<<<dim3(2, 2, 32), 256>>>();
    k1b_finalize<<<1024, 64>>>(rs, Wb, bk, bb);

    k2_mma<0><<<dim3(512, 8), 256, SMEM_K2>>>(nullptr);
    k3_reduce<<<1024, 128>>>();
    k2_mma<1><<<dim3(512, 8), 256, SMEM_K2>>>(out);
}